// round 16
// baseline (speedup 1.0000x reference)
#include <cuda_runtime.h>
#include <cuda_fp16.h>

// Problem constants
#define DIM   96
#define NBIN  64              // 8 theta * 8 phi
#define BSZ   15              // sliding window
#define NVOX  (DIM*DIM*DIM)               // 884736
#define NFLT  ((size_t)NVOX * NBIN)       // 56,623,104
#define LINEH2 (DIM * NBIN / 2)           // half2 per (z,y) line = 3072
#define LINEU2  (DIM * NBIN / 4)          // uint2 per y-row = 1536
#define PLANEU2 (DIM * LINEU2)            // 147456
#define VSTR2 33                          // half2 per x-row in smem (odd -> conflict-free)

// ONE 113 MB fp16 scratch buffer — fits in L2 (126 MB). slideY runs in place.
__device__ __align__(16) __half g_h0[NFLT];

__device__ __forceinline__ unsigned pack2(float a, float b) {
    __half2 h = __float22half2_rn(make_float2(a, b));
    return *reinterpret_cast<unsigned*>(&h);
}
__device__ __forceinline__ float2 unpack2(unsigned u) {
    __half2 h = *reinterpret_cast<__half2*>(&u);
    return __half22float2(h);
}

// ---------------------------------------------------------------------------
// Stage 1: gradients -> soft binning (fp16 smem) -> X sliding sum (half2) -> fp16
// One block (256 thr) per TWO (z,y) lines. Default stores -> L2 resident.
// ---------------------------------------------------------------------------
__global__ void __launch_bounds__(256) binx_kernel(const float* __restrict__ x,
                                                   __half* __restrict__ V)
{
    __shared__ __align__(16) __half2 Vs2[2 * DIM * VSTR2];   // 24.75 KB

    const int tid   = threadIdx.x;
    const int line0 = blockIdx.x * 2;

    {
        uint4* z4 = reinterpret_cast<uint4*>(Vs2);
        const uint4 zz = make_uint4(0u, 0u, 0u, 0u);
        #pragma unroll
        for (int i = tid; i < 2 * DIM * VSTR2 / 4; i += 256) z4[i] = zz;
    }
    __syncthreads();

    if (tid < 2 * DIM) {
        const int l    = tid / DIM;
        const int xi   = tid % DIM;
        const int line = line0 + l;
        const int yi   = line % DIM;
        const int zi   = line / DIM;
        const int v    = (zi * DIM + yi) * DIM + xi;

        const float xp = (xi < DIM - 1) ? x[v + 1]       : 0.f;
        const float xm = (xi > 0)       ? x[v - 1]       : 0.f;
        const float yp = (yi < DIM - 1) ? x[v + DIM]     : 0.f;
        const float ym = (yi > 0)       ? x[v - DIM]     : 0.f;
        const float zp = (zi < DIM - 1) ? x[v + DIM*DIM] : 0.f;
        const float zm = (zi > 0)       ? x[v - DIM*DIM] : 0.f;
        const float gx = xp - xm, gy = yp - ym, gz = zp - zm;

        const float EPS    = 2.2204460492503131e-16f;
        const float TWO_PI = (float)(2.0 * 3.14159265358979323846);
        const float PI_F   = (float)(3.14159265358979323846);
        const float TSTEP  = TWO_PI / 8.0f;
        const float PSTEP  = PI_F   / 8.0f;

        const float r   = sqrtf(gx*gx + gy*gy + gz*gz);
        float theta     = atanf(gy / (gx + EPS));
        const float phi = acosf(gz / (r + EPS));
        if (theta < 0.f) theta += TWO_PI;

        const float t_raw = theta / TSTEP;
        const float p_raw = phi   / PSTEP;

        const float ft = floorf(t_raw);
        int lt = (int)ft;            if (lt == 8) lt = 0;
        int lp = (int)floorf(p_raw); if (lp == 8) lp = 0;
        const int ht = (lt + 1) & 7;
        const int hp = (lp + 1) & 7;

        // theta frac intentionally reused for phi ratios (reference bug, faithful)
        const float frac  = t_raw - ft;
        const float w_lo  = fminf(frac, 1.0f - frac);
        const float w_hi  = 1.0f - w_lo;
        const float wp_lo = (frac == 0.0f) ? 1.0f : w_lo;
        const float wp_hi = 1.0f - wp_lo;

        // 4 target bins are provably distinct -> plain fp16 stores
        __half* row = reinterpret_cast<__half*>(Vs2) + (l * DIM + xi) * (2 * VSTR2);
        row[lt*8 + lp] = __float2half_rn(r * w_lo * wp_lo);
        row[ht*8 + lp] = __float2half_rn(r * w_hi * wp_lo);
        row[lt*8 + hp] = __float2half_rn(r * w_lo * wp_hi);
        row[ht*8 + hp] = __float2half_rn(r * w_hi * wp_hi);
    }
    __syncthreads();

    // running X-window in half2: thread = (line l, bin-word b, segment of 24 x)
    {
        const int l   = tid >> 7;
        const int u   = tid & 127;
        const int b   = u & 31;
        const int seg = u >> 5;
        const int i0  = seg * 24;

        const __half2* row = Vs2 + l * (DIM * VSTR2);

        __half2 w = __float2half2_rn(0.f);
        #pragma unroll
        for (int j = 0; j < BSZ - 1; j++) {
            w = __hadd2(w, row[(i0 + j) * VSTR2 + b]);
        }

        __half2* outv = reinterpret_cast<__half2*>(V) + (size_t)(line0 + l) * LINEH2;
        #pragma unroll
        for (int i = i0; i < i0 + 24; i++) {
            const int hi = i + BSZ - 1;
            if (hi < DIM) w = __hadd2(w, row[hi * VSTR2 + b]);
            outv[i * 32 + b] = w;                 // default store: keep in L2
            w = __hsub2(w, row[i * VSTR2 + b]);
        }
    }
}

// ---------------------------------------------------------------------------
// Stage 2: sliding sum along Y, fp16 -> fp16, IN PLACE on g_h0.
// Fully unrolled with a 15-deep REGISTER ring: each element is loaded exactly
// once; the trailing subtract comes from registers, not memory.
// ---------------------------------------------------------------------------
__global__ void __launch_bounds__(256) slideY_kernel(uint2* __restrict__ buf)
{
    const int t = blockIdx.x * 256 + threadIdx.x;   // < 96*96*16 (grid exact)
    const int q = t & 15;
    const int c = t >> 4;
    const int xi = c % DIM, zi = c / DIM;
    const int base   = zi * PLANEU2 + xi * 16 + q;
    const int stride = LINEU2;

    uint2 ring[BSZ];
    float s0 = 0.f, s1 = 0.f, s2 = 0.f, s3 = 0.f;

    #pragma unroll
    for (int j = 0; j < BSZ - 1; j++) {
        const uint2 u = buf[base + j * stride];
        ring[j] = u;
        const float2 a = unpack2(u.x), b = unpack2(u.y);
        s0 += a.x; s1 += a.y; s2 += b.x; s3 += b.y;
    }

    #pragma unroll
    for (int i = 0; i < DIM; i++) {
        const int hi = i + BSZ - 1;
        if (hi < DIM) {
            const uint2 u = buf[base + hi * stride];
            ring[hi % BSZ] = u;                       // static index after unroll
            const float2 a = unpack2(u.x), b = unpack2(u.y);
            s0 += a.x; s1 += a.y; s2 += b.x; s3 += b.y;
        }
        uint2 o; o.x = pack2(s0, s1); o.y = pack2(s2, s3);
        buf[base + i * stride] = o;                   // in-place, stays in L2
        const uint2 u = ring[i % BSZ];                // trailing from registers
        const float2 a = unpack2(u.x), b = unpack2(u.y);
        s0 -= a.x; s1 -= a.y; s2 -= b.x; s3 -= b.y;
    }
}

// ---------------------------------------------------------------------------
// Stage 3: sliding sum along Z, fp16 (L2-resident) -> fp32 d_out (streaming).
// Same register-ring structure: every input element loaded exactly once.
// ---------------------------------------------------------------------------
__global__ void __launch_bounds__(256) slideZ_kernel(const uint2* __restrict__ in,
                                                     float4* __restrict__ out)
{
    const int t = blockIdx.x * 256 + threadIdx.x;   // < 96*96*16
    const int q = t & 15;
    const int c = t >> 4;
    const int xi = c % DIM, yi = c / DIM;
    const int base   = yi * LINEU2 + xi * 16 + q;
    const int stride = PLANEU2;
    const int obase  = (yi * DIM + xi) * 16 + q;    // + i*96*96*16 per row

    uint2 ring[BSZ];
    float s0 = 0.f, s1 = 0.f, s2 = 0.f, s3 = 0.f;

    #pragma unroll
    for (int j = 0; j < BSZ - 1; j++) {
        const uint2 u = in[base + j * stride];
        ring[j] = u;
        const float2 a = unpack2(u.x), b = unpack2(u.y);
        s0 += a.x; s1 += a.y; s2 += b.x; s3 += b.y;
    }

    #pragma unroll
    for (int i = 0; i < DIM; i++) {
        const int hi = i + BSZ - 1;
        if (hi < DIM) {
            const uint2 u = in[base + hi * stride];
            ring[hi % BSZ] = u;
            const float2 a = unpack2(u.x), b = unpack2(u.y);
            s0 += a.x; s1 += a.y; s2 += b.x; s3 += b.y;
        }
        __stcs(&out[obase + i * (DIM * DIM * 16)],
               make_float4(s0, s1, s2, s3));          // streaming final output
        const uint2 u = ring[i % BSZ];                // trailing from registers
        const float2 a = unpack2(u.x), b = unpack2(u.y);
        s0 -= a.x; s1 -= a.y; s2 -= b.x; s3 -= b.y;
    }
}

// ---------------------------------------------------------------------------
extern "C" void kernel_launch(void* const* d_in, const int* in_sizes, int n_in,
                              void* d_out, int out_size)
{
    const float* x = (const float*)d_in[0];

    void* p0 = nullptr;
    cudaGetSymbolAddress(&p0, g_h0);

    const int binBlocks   = DIM * DIM / 2;               // 4608 (2 lines/block)
    const int slideBlocks = (DIM * DIM * 16) / 256;      // 576

    binx_kernel<<<binBlocks, 256>>>(x, (__half*)p0);                        // x -> Xsum(h0)
    slideY_kernel<<<slideBlocks, 256>>>((uint2*)p0);                        // h0 in-place
    slideZ_kernel<<<slideBlocks, 256>>>((const uint2*)p0, (float4*)d_out);  // h0 -> out
}

// round 17
// speedup vs baseline: 1.1093x; 1.1093x over previous
#include <cuda_runtime.h>
#include <cuda_fp16.h>

// Problem constants
#define DIM   96
#define NBIN  64              // 8 theta * 8 phi
#define BSZ   15              // sliding window
#define NVOX  (DIM*DIM*DIM)               // 884736
#define NFLT  ((size_t)NVOX * NBIN)       // 56,623,104
#define LINEH2 (DIM * NBIN / 2)           // half2 per (z,y) line = 3072
#define LINEU2  (DIM * NBIN / 4)          // uint2 per y-row = 1536
#define PLANEU2 (DIM * LINEU2)            // 147456
#define VSTR2 33                          // half2 per x-row in smem (odd -> conflict-free)

// ONE 113 MB fp16 scratch buffer — fits in L2 (126 MB). slideY runs in place.
__device__ __align__(16) __half g_h0[NFLT];

__device__ __forceinline__ unsigned pack2(float a, float b) {
    __half2 h = __float22half2_rn(make_float2(a, b));
    return *reinterpret_cast<unsigned*>(&h);
}
__device__ __forceinline__ float2 unpack2(unsigned u) {
    __half2 h = *reinterpret_cast<__half2*>(&u);
    return __half22float2(h);
}

// ---------------------------------------------------------------------------
// Stage 1: gradients -> soft binning (fp16 smem) -> X sliding sum (half2) -> fp16
// One block (256 thr) per TWO (z,y) lines. Default stores -> L2 resident.
// ---------------------------------------------------------------------------
__global__ void __launch_bounds__(256) binx_kernel(const float* __restrict__ x,
                                                   __half* __restrict__ V)
{
    __shared__ __align__(16) __half2 Vs2[2 * DIM * VSTR2];   // 24.75 KB

    const int tid   = threadIdx.x;
    const int line0 = blockIdx.x * 2;

    {
        uint4* z4 = reinterpret_cast<uint4*>(Vs2);
        const uint4 zz = make_uint4(0u, 0u, 0u, 0u);
        #pragma unroll
        for (int i = tid; i < 2 * DIM * VSTR2 / 4; i += 256) z4[i] = zz;
    }
    __syncthreads();

    if (tid < 2 * DIM) {
        const int l    = tid / DIM;
        const int xi   = tid % DIM;
        const int line = line0 + l;
        const int yi   = line % DIM;
        const int zi   = line / DIM;
        const int v    = (zi * DIM + yi) * DIM + xi;

        const float xp = (xi < DIM - 1) ? x[v + 1]       : 0.f;
        const float xm = (xi > 0)       ? x[v - 1]       : 0.f;
        const float yp = (yi < DIM - 1) ? x[v + DIM]     : 0.f;
        const float ym = (yi > 0)       ? x[v - DIM]     : 0.f;
        const float zp = (zi < DIM - 1) ? x[v + DIM*DIM] : 0.f;
        const float zm = (zi > 0)       ? x[v - DIM*DIM] : 0.f;
        const float gx = xp - xm, gy = yp - ym, gz = zp - zm;

        const float EPS    = 2.2204460492503131e-16f;
        const float TWO_PI = (float)(2.0 * 3.14159265358979323846);
        const float PI_F   = (float)(3.14159265358979323846);
        const float TSTEP  = TWO_PI / 8.0f;
        const float PSTEP  = PI_F   / 8.0f;

        const float r   = sqrtf(gx*gx + gy*gy + gz*gz);
        float theta     = atanf(gy / (gx + EPS));
        const float phi = acosf(gz / (r + EPS));
        if (theta < 0.f) theta += TWO_PI;

        const float t_raw = theta / TSTEP;
        const float p_raw = phi   / PSTEP;

        const float ft = floorf(t_raw);
        int lt = (int)ft;            if (lt == 8) lt = 0;
        int lp = (int)floorf(p_raw); if (lp == 8) lp = 0;
        const int ht = (lt + 1) & 7;
        const int hp = (lp + 1) & 7;

        // theta frac intentionally reused for phi ratios (reference bug, faithful)
        const float frac  = t_raw - ft;
        const float w_lo  = fminf(frac, 1.0f - frac);
        const float w_hi  = 1.0f - w_lo;
        const float wp_lo = (frac == 0.0f) ? 1.0f : w_lo;
        const float wp_hi = 1.0f - wp_lo;

        // 4 target bins are provably distinct -> plain fp16 stores
        __half* row = reinterpret_cast<__half*>(Vs2) + (l * DIM + xi) * (2 * VSTR2);
        row[lt*8 + lp] = __float2half_rn(r * w_lo * wp_lo);
        row[ht*8 + lp] = __float2half_rn(r * w_hi * wp_lo);
        row[lt*8 + hp] = __float2half_rn(r * w_lo * wp_hi);
        row[ht*8 + hp] = __float2half_rn(r * w_hi * wp_hi);
    }
    __syncthreads();

    // running X-window in half2: thread = (line l, bin-word b, segment of 24 x)
    {
        const int l   = tid >> 7;
        const int u   = tid & 127;
        const int b   = u & 31;
        const int seg = u >> 5;
        const int i0  = seg * 24;

        const __half2* row = Vs2 + l * (DIM * VSTR2);

        __half2 w = __float2half2_rn(0.f);
        #pragma unroll
        for (int j = 0; j < BSZ - 1; j++) {
            w = __hadd2(w, row[(i0 + j) * VSTR2 + b]);
        }

        __half2* outv = reinterpret_cast<__half2*>(V) + (size_t)(line0 + l) * LINEH2;
        #pragma unroll
        for (int i = i0; i < i0 + 24; i++) {
            const int hi = i + BSZ - 1;
            if (hi < DIM) w = __hadd2(w, row[hi * VSTR2 + b]);
            outv[i * 32 + b] = w;                 // default store: keep in L2
            w = __hsub2(w, row[i * VSTR2 + b]);
        }
    }
}

// ---------------------------------------------------------------------------
// Stage 2: sliding sum along Y, fp16 -> fp16, IN PLACE on g_h0.
// (exact R15 form — at LTS cap; trailing read before same-address write)
// ---------------------------------------------------------------------------
__global__ void __launch_bounds__(256) slideY_kernel(uint2* __restrict__ buf)
{
    const int t = blockIdx.x * 256 + threadIdx.x;   // < 96*96*16 (grid exact)
    const int q = t & 15;
    const int c = t >> 4;
    const int xi = c % DIM, zi = c / DIM;
    const int base   = zi * PLANEU2 + xi * 16 + q;
    const int stride = LINEU2;

    float s0 = 0.f, s1 = 0.f, s2 = 0.f, s3 = 0.f;
    #pragma unroll
    for (int j = 0; j < BSZ - 1; j++) {
        const uint2 u = buf[base + j * stride];
        const float2 a = unpack2(u.x), b = unpack2(u.y);
        s0 += a.x; s1 += a.y; s2 += b.x; s3 += b.y;
    }

    int off = base;
    #pragma unroll 4
    for (int i = 0; i < DIM; i++) {
        if (i + BSZ - 1 < DIM) {
            const uint2 u = buf[base + (i + BSZ - 1) * stride];
            const float2 a = unpack2(u.x), b = unpack2(u.y);
            s0 += a.x; s1 += a.y; s2 += b.x; s3 += b.y;
        }
        // read trailing (old) BEFORE overwriting the same address
        const uint2 u = buf[off];
        const float2 a = unpack2(u.x), b = unpack2(u.y);
        uint2 o; o.x = pack2(s0, s1); o.y = pack2(s2, s3);
        buf[off] = o;                                // in-place, stays in L2
        s0 -= a.x; s1 -= a.y; s2 -= b.x; s3 -= b.y;
        off += stride;
    }
}

// ---------------------------------------------------------------------------
// Stage 3: sliding sum along Z, fp16 (L2-resident) -> fp32 d_out (streaming).
// Split: each thread handles HALF a z-column (48 outputs) -> 2x parallelism,
// half the serial chain; extra warm-up reads are L2 hits (non-binding).
// ---------------------------------------------------------------------------
__global__ void __launch_bounds__(256) slideZ_kernel(const uint2* __restrict__ in,
                                                     float4* __restrict__ out)
{
    const int t = blockIdx.x * 256 + threadIdx.x;   // < 96*96*16*2
    const int q = t & 15;
    const int c = t >> 4;
    const int xi  = c % DIM;
    const int rem = c / DIM;
    const int yi  = rem % DIM;
    const int seg = rem / DIM;                      // 0..1 (z-half)
    const int z0  = seg * (DIM / 2);                // 0 or 48

    const int base   = yi * LINEU2 + xi * 16 + q;
    const int stride = PLANEU2;
    const int obase  = (yi * DIM + xi) * 16 + q;

    float s0 = 0.f, s1 = 0.f, s2 = 0.f, s3 = 0.f;
    #pragma unroll
    for (int j = 0; j < BSZ - 1; j++) {             // z0..z0+13, max 61 < 96
        const uint2 u = in[base + (z0 + j) * stride];
        const float2 a = unpack2(u.x), b = unpack2(u.y);
        s0 += a.x; s1 += a.y; s2 += b.x; s3 += b.y;
    }

    #pragma unroll 4
    for (int i = 0; i < DIM / 2; i++) {
        const int z  = z0 + i;
        const int hi = z + BSZ - 1;
        if (hi < DIM) {
            const uint2 u = in[base + hi * stride];
            const float2 a = unpack2(u.x), b = unpack2(u.y);
            s0 += a.x; s1 += a.y; s2 += b.x; s3 += b.y;
        }
        __stcs(&out[obase + z * (DIM * DIM * 16)],
               make_float4(s0, s1, s2, s3));        // streaming final output
        const uint2 u = in[base + z * stride];      // trailing (L1/L2 hit)
        const float2 a = unpack2(u.x), b = unpack2(u.y);
        s0 -= a.x; s1 -= a.y; s2 -= b.x; s3 -= b.y;
    }
}

// ---------------------------------------------------------------------------
extern "C" void kernel_launch(void* const* d_in, const int* in_sizes, int n_in,
                              void* d_out, int out_size)
{
    const float* x = (const float*)d_in[0];

    void* p0 = nullptr;
    cudaGetSymbolAddress(&p0, g_h0);

    const int binBlocks    = DIM * DIM / 2;               // 4608 (2 lines/block)
    const int slideYBlocks = (DIM * DIM * 16) / 256;      // 576
    const int slideZBlocks = (DIM * DIM * 16 * 2) / 256;  // 1152 (z split in 2)

    binx_kernel<<<binBlocks, 256>>>(x, (__half*)p0);                        // x -> Xsum(h0)
    slideY_kernel<<<slideYBlocks, 256>>>((uint2*)p0);                       // h0 in-place
    slideZ_kernel<<<slideZBlocks, 256>>>((const uint2*)p0, (float4*)d_out); // h0 -> out
}